// round 14
// baseline (speedup 1.0000x reference)
#include <cuda_runtime.h>
#include <cuda_fp16.h>

#define NTOK      64
#define DIMC      128
#define NHEADS    4
#define NWIN      256
#define NWINDOWS  8192
#define ATT_SCALE 0.17677669529663687f
#define LOG2E     1.4426950408889634f

// ---------------- device scratch ----------------
// Pair-packed weight fragments: [nbp][kt][lane] -> uint4
__device__ uint4 g_wqkv4[24 * 8 * 32];    // 384 rows -> 48 n-blocks -> 24 pairs
__device__ uint4 g_wproj4[8 * 8 * 32];    // 128 rows -> 16 n-blocks -> 8 pairs
// Fragment-packed bias+mask (pre-multiplied by log2e): [w][h][mh][mt][nt][lane] -> float4
__device__ float4 g_bmf[NWIN * NHEADS * 2 * 2 * 8 * 32];   // 16 MB, L2-resident

// ---------------- merged prep kernel ----------------
__global__ void prep_all_k(const float* __restrict__ mask,
                           const float* __restrict__ bias_table,
                           const int* __restrict__ rel_index,
                           const float* __restrict__ qkv_w,
                           const float* __restrict__ proj_w) {
    int e = blockIdx.x * blockDim.x + threadIdx.x;   // 2^20 threads
    if (e < 24 * 8 * 32) {
        int lane = e & 31, kt = (e >> 5) & 7, nbp = e >> 8;
        int n0 = nbp * 16 + (lane >> 2);
        int n1 = n0 + 8;
        int k0 = kt * 16 + 2 * (lane & 3);
        const float* W0 = qkv_w + n0 * DIMC + k0;
        const float* W1 = qkv_w + n1 * DIMC + k0;
        __half2 a0 = __floats2half2_rn(W0[0], W0[1]);
        __half2 a1 = __floats2half2_rn(W0[8], W0[9]);
        __half2 b0 = __floats2half2_rn(W1[0], W1[1]);
        __half2 b1 = __floats2half2_rn(W1[8], W1[9]);
        g_wqkv4[e] = make_uint4(*(unsigned*)&a0, *(unsigned*)&a1,
                                *(unsigned*)&b0, *(unsigned*)&b1);
    }
    if (e < 8 * 8 * 32) {
        int lane = e & 31, kt = (e >> 5) & 7, nbp = e >> 8;
        int n0 = nbp * 16 + (lane >> 2);
        int n1 = n0 + 8;
        int k0 = kt * 16 + 2 * (lane & 3);
        const float* W0 = proj_w + n0 * DIMC + k0;
        const float* W1 = proj_w + n1 * DIMC + k0;
        __half2 a0 = __floats2half2_rn(W0[0], W0[1]);
        __half2 a1 = __floats2half2_rn(W0[8], W0[9]);
        __half2 b0 = __floats2half2_rn(W1[0], W1[1]);
        __half2 b1 = __floats2half2_rn(W1[8], W1[9]);
        g_wproj4[e] = make_uint4(*(unsigned*)&a0, *(unsigned*)&a1,
                                 *(unsigned*)&b0, *(unsigned*)&b1);
    }
    // bmf: e linear over [w][h][mh][mt][nt][lane]; values pre-scaled by log2e
    {
        int lane = e & 31;
        int nt = (e >> 5) & 7;
        int mt = (e >> 8) & 1;
        int mh = (e >> 9) & 1;
        int h  = (e >> 10) & 3;
        int w  = e >> 12;
        int r0  = mh * 32 + mt * 16 + (lane >> 2);
        int col = nt * 8 + (lane & 3) * 2;
        const float* mw = mask + (size_t)w * 64 * 64;
        float v00 = mw[r0 * 64 + col]       + bias_table[rel_index[r0 * 64 + col] * NHEADS + h];
        float v01 = mw[r0 * 64 + col + 1]   + bias_table[rel_index[r0 * 64 + col + 1] * NHEADS + h];
        float v10 = mw[(r0 + 8) * 64 + col] + bias_table[rel_index[(r0 + 8) * 64 + col] * NHEADS + h];
        float v11 = mw[(r0 + 8) * 64 + col + 1]
                  + bias_table[rel_index[(r0 + 8) * 64 + col + 1] * NHEADS + h];
        g_bmf[e] = make_float4(v00 * LOG2E, v01 * LOG2E, v10 * LOG2E, v11 * LOG2E);
    }
}

// ---------------- helpers ----------------
__device__ __forceinline__ unsigned h2u(__half2 v) {
    return *reinterpret_cast<unsigned*>(&v);
}
__device__ __forceinline__ void mma_16816(float c[4], const unsigned a[4],
                                          const unsigned b0, const unsigned b1) {
    asm volatile(
        "mma.sync.aligned.m16n8k16.row.col.f32.f16.f16.f32 "
        "{%0,%1,%2,%3}, {%4,%5,%6,%7}, {%8,%9}, {%0,%1,%2,%3};\n"
        : "+f"(c[0]), "+f"(c[1]), "+f"(c[2]), "+f"(c[3])
        : "r"(a[0]), "r"(a[1]), "r"(a[2]), "r"(a[3]), "r"(b0), "r"(b1));
}
__device__ __forceinline__ void ldsm4(unsigned r[4], const __half* p) {
    unsigned a = (unsigned)__cvta_generic_to_shared(p);
    asm volatile("ldmatrix.sync.aligned.m8n8.x4.shared.b16 {%0,%1,%2,%3}, [%4];\n"
                 : "=r"(r[0]), "=r"(r[1]), "=r"(r[2]), "=r"(r[3]) : "r"(a));
}

// SMEM layout (bytes)
#define SM_XH  0       // [64][136] half = 17408  -> later oh
#define SM_KH  17408   // [64][136] half
#define SM_VT  34816   // [128][72] half = 18432 (vt[d][m])
#define SM_OH  0       // overlays xh
#define SMEM_BYTES 53248

// ---------------- main fused kernel: 1 window per CTA, 2 CTAs/SM ----------------
__global__ void __launch_bounds__(256, 2)
swin_attn_kernel(const float* __restrict__ x,
                 const float* __restrict__ qkv_b,
                 const float* __restrict__ proj_b,
                 float* __restrict__ out) {
    extern __shared__ char smem[];
    __half* xh = (__half*)(smem + SM_XH);
    __half* kh = (__half*)(smem + SM_KH);
    __half* vt = (__half*)(smem + SM_VT);
    __half* oh = (__half*)(smem + SM_OH);

    const int tid  = threadIdx.x;
    const int lane = tid & 31;
    const int warp = tid >> 5;
    const int l4   = lane >> 2;
    const int lm   = lane & 3;
    const int b    = blockIdx.x;

    const int arow = (lane & 7) + (lane & 8);
    const int acol = (lane & 16) ? 8 : 0;
    const int brow = (lane & 7) + ((lane & 16) ? 8 : 0);
    const int bcol = (lane & 8) ? 8 : 0;

    // unified warp mapping for ALL phases: head h, M-half mh
    const int h  = warp >> 1;
    const int mh = warp & 1;

    // ---- phase 0: x tile -> fp16 smem ----
    {
        const float4* xg = (const float4*)(x + (size_t)b * NTOK * DIMC);
#pragma unroll
        for (int i = 0; i < 8; ++i) {
            int idx = tid + i * 256;
            float4 v = __ldcs(xg + idx);
            int row = idx >> 5;
            int col = (idx & 31) << 2;
            __half2 h0 = __floats2half2_rn(v.x, v.y);
            __half2 h1 = __floats2half2_rn(v.z, v.w);
            *(uint2*)(xh + row * 136 + col) = make_uint2(h2u(h0), h2u(h1));
        }
    }
    __syncthreads();   // sync #1

    // q A-frags + own-half K B-frags, kept in registers across sync #2
    unsigned aq[2][2][4];
    unsigned kb[2][4][2];   // [mt][nb][c01/c23] fp16 K values (own M-half)

    // ---- phase 1: QKV GEMM; warp computes its OWN q/k/v head slices ----
    {
        float cq[2][4][4], ck[2][4][4], cv[2][4][4];
#pragma unroll
        for (int a = 0; a < 2; ++a)
#pragma unroll
            for (int t = 0; t < 4; ++t)
#pragma unroll
                for (int r = 0; r < 4; ++r) {
                    cq[a][t][r] = 0.f; ck[a][t][r] = 0.f; cv[a][t][r] = 0.f;
                }

#pragma unroll
        for (int ktg = 0; ktg < 8; ++ktg) {
            int kc = ktg * 16;
            unsigned a0[4], a1[4];
            ldsm4(a0, xh + (mh * 32 + arow) * 136 + kc + acol);
            ldsm4(a1, xh + (mh * 32 + 16 + arow) * 136 + kc + acol);
#pragma unroll
            for (int p = 0; p < 2; ++p) {       // q
                uint4 f = __ldg(&g_wqkv4[(((h * 2 + p) * 8 + ktg) << 5) + lane]);
                mma_16816(cq[0][2 * p],     a0, f.x, f.y);
                mma_16816(cq[1][2 * p],     a1, f.x, f.y);
                mma_16816(cq[0][2 * p + 1], a0, f.z, f.w);
                mma_16816(cq[1][2 * p + 1], a1, f.z, f.w);
            }
#pragma unroll
            for (int p = 0; p < 2; ++p) {       // k
                uint4 f = __ldg(&g_wqkv4[(((8 + h * 2 + p) * 8 + ktg) << 5) + lane]);
                mma_16816(ck[0][2 * p],     a0, f.x, f.y);
                mma_16816(ck[1][2 * p],     a1, f.x, f.y);
                mma_16816(ck[0][2 * p + 1], a0, f.z, f.w);
                mma_16816(ck[1][2 * p + 1], a1, f.z, f.w);
            }
#pragma unroll
            for (int p = 0; p < 2; ++p) {       // v
                uint4 f = __ldg(&g_wqkv4[(((16 + h * 2 + p) * 8 + ktg) << 5) + lane]);
                mma_16816(cv[0][2 * p],     a0, f.x, f.y);
                mma_16816(cv[1][2 * p],     a1, f.x, f.y);
                mma_16816(cv[0][2 * p + 1], a0, f.z, f.w);
                mma_16816(cv[1][2 * p + 1], a1, f.z, f.w);
            }
        }

        // epilogue: k -> kh (+ keep own-half B-frags in kb)
#pragma unroll
        for (int mt = 0; mt < 2; ++mt)
#pragma unroll
            for (int nb = 0; nb < 4; ++nb) {
                int col = h * 32 + nb * 8 + lm * 2;
                int r0 = mh * 32 + mt * 16 + l4;
                float2 bv = *(const float2*)(qkv_b + 128 + col);
                __half2 h0 = __floats2half2_rn(ck[mt][nb][0] + bv.x, ck[mt][nb][1] + bv.y);
                __half2 h1 = __floats2half2_rn(ck[mt][nb][2] + bv.x, ck[mt][nb][3] + bv.y);
                kb[mt][nb][0] = h2u(h0);
                kb[mt][nb][1] = h2u(h1);
                *(__half2*)(kh + r0 * 136 + col) = h0;
                *(__half2*)(kh + (r0 + 8) * 136 + col) = h1;
            }
        // epilogue: v -> vt (transposed)
#pragma unroll
        for (int mt = 0; mt < 2; ++mt)
#pragma unroll
            for (int nb = 0; nb < 4; ++nb) {
                int d  = h * 32 + nb * 8 + lm * 2;
                int r0 = mh * 32 + mt * 16 + l4;
                float2 bv = *(const float2*)(qkv_b + 256 + d);
                vt[d * 72 + r0]           = __float2half_rn(cv[mt][nb][0] + bv.x);
                vt[(d + 1) * 72 + r0]     = __float2half_rn(cv[mt][nb][1] + bv.y);
                vt[d * 72 + r0 + 8]       = __float2half_rn(cv[mt][nb][2] + bv.x);
                vt[(d + 1) * 72 + r0 + 8] = __float2half_rn(cv[mt][nb][3] + bv.y);
            }
        // epilogue: q -> A-frags in registers (bias + scale folded, log2 domain)
        const float qsc = ATT_SCALE * LOG2E;
#pragma unroll
        for (int mt = 0; mt < 2; ++mt)
#pragma unroll
            for (int kt = 0; kt < 2; ++kt) {
                int col0 = h * 32 + (2 * kt) * 8 + lm * 2;
                float2 b0 = *(const float2*)(qkv_b + col0);
                float2 b1 = *(const float2*)(qkv_b + col0 + 8);
                aq[mt][kt][0] = h2u(__floats2half2_rn((cq[mt][2 * kt][0] + b0.x) * qsc,
                                                      (cq[mt][2 * kt][1] + b0.y) * qsc));
                aq[mt][kt][1] = h2u(__floats2half2_rn((cq[mt][2 * kt][2] + b0.x) * qsc,
                                                      (cq[mt][2 * kt][3] + b0.y) * qsc));
                aq[mt][kt][2] = h2u(__floats2half2_rn((cq[mt][2 * kt + 1][0] + b1.x) * qsc,
                                                      (cq[mt][2 * kt + 1][1] + b1.y) * qsc));
                aq[mt][kt][3] = h2u(__floats2half2_rn((cq[mt][2 * kt + 1][2] + b1.x) * qsc,
                                                      (cq[mt][2 * kt + 1][3] + b1.y) * qsc));
            }
    }
    __syncthreads();   // sync #2

    // ---- phase 2: attention (q in regs; own-half K B-frags in regs) ----
    {
        const int rowbase = mh * 32;

        float s[2][8][4];
#pragma unroll
        for (int a = 0; a < 2; ++a)
#pragma unroll
            for (int t = 0; t < 8; ++t)
#pragma unroll
                for (int r = 0; r < 4; ++r) s[a][t][r] = 0.f;

        // S = Q @ K^T: own M-half n-blocks from kb registers, partner via smem
#pragma unroll
        for (int kt = 0; kt < 2; ++kt) {
            int kc = h * 32 + kt * 16;
            if (mh == 0) {
                mma_16816(s[0][0], aq[0][kt], kb[0][2 * kt][0], kb[0][2 * kt + 1][0]);
                mma_16816(s[1][0], aq[1][kt], kb[0][2 * kt][0], kb[0][2 * kt + 1][0]);
                mma_16816(s[0][1], aq[0][kt], kb[0][2 * kt][1], kb[0][2 * kt + 1][1]);
                mma_16816(s[1][1], aq[1][kt], kb[0][2 * kt][1], kb[0][2 * kt + 1][1]);
                mma_16816(s[0][2], aq[0][kt], kb[1][2 * kt][0], kb[1][2 * kt + 1][0]);
                mma_16816(s[1][2], aq[1][kt], kb[1][2 * kt][0], kb[1][2 * kt + 1][0]);
                mma_16816(s[0][3], aq[0][kt], kb[1][2 * kt][1], kb[1][2 * kt + 1][1]);
                mma_16816(s[1][3], aq[1][kt], kb[1][2 * kt][1], kb[1][2 * kt + 1][1]);
#pragma unroll
                for (int pm = 0; pm < 2; ++pm) {
                    unsigned r[4];
                    ldsm4(r, kh + ((2 + pm) * 16 + brow) * 136 + kc + bcol);
                    mma_16816(s[0][4 + 2 * pm], aq[0][kt], r[0], r[1]);
                    mma_16816(s[1][4 + 2 * pm], aq[1][kt], r[0], r[1]);
                    mma_16816(s[0][5 + 2 * pm], aq[0][kt], r[2], r[3]);
                    mma_16816(s[1][5 + 2 * pm], aq[1][kt], r[2], r[3]);
                }
            } else {
#pragma unroll
                for (int pm = 0; pm < 2; ++pm) {
                    unsigned r[4];
                    ldsm4(r, kh + (pm * 16 + brow) * 136 + kc + bcol);
                    mma_16816(s[0][2 * pm],     aq[0][kt], r[0], r[1]);
                    mma_16816(s[1][2 * pm],     aq[1][kt], r[0], r[1]);
                    mma_16816(s[0][2 * pm + 1], aq[0][kt], r[2], r[3]);
                    mma_16816(s[1][2 * pm + 1], aq[1][kt], r[2], r[3]);
                }
                mma_16816(s[0][4], aq[0][kt], kb[0][2 * kt][0], kb[0][2 * kt + 1][0]);
                mma_16816(s[1][4], aq[1][kt], kb[0][2 * kt][0], kb[0][2 * kt + 1][0]);
                mma_16816(s[0][5], aq[0][kt], kb[0][2 * kt][1], kb[0][2 * kt + 1][1]);
                mma_16816(s[1][5], aq[1][kt], kb[0][2 * kt][1], kb[0][2 * kt + 1][1]);
                mma_16816(s[0][6], aq[0][kt], kb[1][2 * kt][0], kb[1][2 * kt + 1][0]);
                mma_16816(s[1][6], aq[1][kt], kb[1][2 * kt][0], kb[1][2 * kt + 1][0]);
                mma_16816(s[0][7], aq[0][kt], kb[1][2 * kt][1], kb[1][2 * kt + 1][1]);
                mma_16816(s[1][7], aq[1][kt], kb[1][2 * kt][1], kb[1][2 * kt + 1][1]);
            }
        }

        // + (bias+mask)*log2e, softmax in exp2 domain
        const float4* bmf = g_bmf
            + ((((size_t)(b & 255) * NHEADS + h) * 2 + mh) * 2) * 8 * 32;
        float rmax[4] = {-1e30f, -1e30f, -1e30f, -1e30f};
#pragma unroll
        for (int mt = 0; mt < 2; ++mt) {
#pragma unroll
            for (int nt = 0; nt < 8; ++nt) {
                float4 bv = __ldg(&bmf[(mt * 8 + nt) * 32 + lane]);
                s[mt][nt][0] += bv.x;
                s[mt][nt][1] += bv.y;
                s[mt][nt][2] += bv.z;
                s[mt][nt][3] += bv.w;
                rmax[mt * 2]     = fmaxf(rmax[mt * 2],     fmaxf(s[mt][nt][0], s[mt][nt][1]));
                rmax[mt * 2 + 1] = fmaxf(rmax[mt * 2 + 1], fmaxf(s[mt][nt][2], s[mt][nt][3]));
            }
        }
#pragma unroll
        for (int i = 0; i < 4; ++i) {
            rmax[i] = fmaxf(rmax[i], __shfl_xor_sync(0xffffffffu, rmax[i], 1));
            rmax[i] = fmaxf(rmax[i], __shfl_xor_sync(0xffffffffu, rmax[i], 2));
        }
        float rsum[4] = {0.f, 0.f, 0.f, 0.f};
#pragma unroll
        for (int mt = 0; mt < 2; ++mt)
#pragma unroll
            for (int nt = 0; nt < 8; ++nt) {
                s[mt][nt][0] = exp2f(s[mt][nt][0] - rmax[mt * 2]);
                s[mt][nt][1] = exp2f(s[mt][nt][1] - rmax[mt * 2]);
                s[mt][nt][2] = exp2f(s[mt][nt][2] - rmax[mt * 2 + 1]);
                s[mt][nt][3] = exp2f(s[mt][nt][3] - rmax[mt * 2 + 1]);
                rsum[mt * 2]     += s[mt][nt][0] + s[mt][nt][1];
                rsum[mt * 2 + 1] += s[mt][nt][2] + s[mt][nt][3];
            }
#pragma unroll
        for (int i = 0; i < 4; ++i) {
            rsum[i] += __shfl_xor_sync(0xffffffffu, rsum[i], 1);
            rsum[i] += __shfl_xor_sync(0xffffffffu, rsum[i], 2);
        }
        float rinv[4];
#pragma unroll
        for (int i = 0; i < 4; ++i) rinv[i] = 1.0f / rsum[i];

        // repack normalized P into A fragments
        unsigned pa[2][4][4];
#pragma unroll
        for (int mt = 0; mt < 2; ++mt)
#pragma unroll
            for (int k2 = 0; k2 < 4; ++k2) {
                pa[mt][k2][0] = h2u(__floats2half2_rn(s[mt][2 * k2][0] * rinv[2 * mt],
                                                      s[mt][2 * k2][1] * rinv[2 * mt]));
                pa[mt][k2][1] = h2u(__floats2half2_rn(s[mt][2 * k2][2] * rinv[2 * mt + 1],
                                                      s[mt][2 * k2][3] * rinv[2 * mt + 1]));
                pa[mt][k2][2] = h2u(__floats2half2_rn(s[mt][2 * k2 + 1][0] * rinv[2 * mt],
                                                      s[mt][2 * k2 + 1][1] * rinv[2 * mt]));
                pa[mt][k2][3] = h2u(__floats2half2_rn(s[mt][2 * k2 + 1][2] * rinv[2 * mt + 1],
                                                      s[mt][2 * k2 + 1][3] * rinv[2 * mt + 1]));
            }

        // O = P @ V (vt transposed layout)
        float o[2][4][4];
#pragma unroll
        for (int a = 0; a < 2; ++a)
#pragma unroll
            for (int t = 0; t < 4; ++t)
#pragma unroll
                for (int r = 0; r < 4; ++r) o[a][t][r] = 0.f;
#pragma unroll
        for (int k2 = 0; k2 < 4; ++k2)
#pragma unroll
            for (int p = 0; p < 2; ++p) {
                unsigned r[4];
                ldsm4(r, vt + (h * 32 + p * 16 + brow) * 72 + k2 * 16 + bcol);
                mma_16816(o[0][2 * p],     pa[0][k2], r[0], r[1]);
                mma_16816(o[1][2 * p],     pa[1][k2], r[0], r[1]);
                mma_16816(o[0][2 * p + 1], pa[0][k2], r[2], r[3]);
                mma_16816(o[1][2 * p + 1], pa[1][k2], r[2], r[3]);
            }
#pragma unroll
        for (int mt = 0; mt < 2; ++mt)
#pragma unroll
            for (int nt = 0; nt < 4; ++nt) {
                int col = h * 32 + nt * 8 + lm * 2;
                int r0 = rowbase + mt * 16 + l4;
                *(__half2*)(oh + r0 * 136 + col) =
                    __floats2half2_rn(o[mt][nt][0], o[mt][nt][1]);
                *(__half2*)(oh + (r0 + 8) * 136 + col) =
                    __floats2half2_rn(o[mt][nt][2], o[mt][nt][3]);
            }
    }
    __syncthreads();   // sync #3

    // ---- phase 3: out = O @ Wproj^T + proj_b (pure ldsm, R12 form) ----
    {
        float c[2][4][4];
#pragma unroll
        for (int a = 0; a < 2; ++a)
#pragma unroll
            for (int t = 0; t < 4; ++t)
#pragma unroll
                for (int r = 0; r < 4; ++r) c[a][t][r] = 0.f;

#pragma unroll
        for (int ktg = 0; ktg < 8; ++ktg) {
            int kc = ktg * 16;
            unsigned a0[4], a1[4];
            ldsm4(a0, oh + (mh * 32 + arow) * 136 + kc + acol);
            ldsm4(a1, oh + (mh * 32 + 16 + arow) * 136 + kc + acol);
#pragma unroll
            for (int p = 0; p < 2; ++p) {
                uint4 f = __ldg(&g_wproj4[(((h * 2 + p) * 8 + ktg) << 5) + lane]);
                mma_16816(c[0][2 * p],     a0, f.x, f.y);
                mma_16816(c[1][2 * p],     a1, f.x, f.y);
                mma_16816(c[0][2 * p + 1], a0, f.z, f.w);
                mma_16816(c[1][2 * p + 1], a1, f.z, f.w);
            }
        }

        float* og = out + (size_t)b * NTOK * DIMC;
#pragma unroll
        for (int mt = 0; mt < 2; ++mt)
#pragma unroll
            for (int nt = 0; nt < 4; ++nt) {
                int col = h * 32 + nt * 8 + lm * 2;
                int r0 = mh * 32 + mt * 16 + l4;
                float2 pb = *(const float2*)(proj_b + col);
                float2 v0 = {c[mt][nt][0] + pb.x, c[mt][nt][1] + pb.y};
                float2 v1 = {c[mt][nt][2] + pb.x, c[mt][nt][3] + pb.y};
                __stcs((float2*)(og + r0 * 128 + col), v0);
                __stcs((float2*)(og + (r0 + 8) * 128 + col), v1);
            }
    }
}

// ---------------- launch ----------------
extern "C" void kernel_launch(void* const* d_in, const int* in_sizes, int n_in,
                              void* d_out, int out_size) {
    const float* x       = (const float*)d_in[0];
    const float* mask    = (const float*)d_in[1];
    const float* qkv_w   = (const float*)d_in[2];
    const float* qkv_b   = (const float*)d_in[3];
    const float* proj_w  = (const float*)d_in[4];
    const float* proj_b  = (const float*)d_in[5];
    const float* bias_t  = (const float*)d_in[6];
    const int*   rel_idx = (const int*)d_in[7];
    float* out = (float*)d_out;

    prep_all_k<<<4096, 256>>>(mask, bias_t, rel_idx, qkv_w, proj_w);

    cudaFuncSetAttribute(swin_attn_kernel,
                         cudaFuncAttributeMaxDynamicSharedMemorySize, SMEM_BYTES);
    swin_attn_kernel<<<NWINDOWS, 256, SMEM_BYTES>>>(x, qkv_b, proj_b, out);
}

// round 15
// speedup vs baseline: 1.1394x; 1.1394x over previous
#include <cuda_runtime.h>
#include <cuda_fp16.h>

#define NTOK      64
#define DIMC      128
#define NHEADS    4
#define NWIN      256
#define NWINDOWS  8192
#define ATT_SCALE 0.17677669529663687f
#define LOG2E     1.4426950408889634f

// ---------------- device scratch ----------------
// Pair-packed weight fragments: [nbp][kt][lane] -> uint4
__device__ uint4 g_wqkv4[24 * 8 * 32];    // 384 rows -> 48 n-blocks -> 24 pairs
__device__ uint4 g_wproj4[8 * 8 * 32];    // 128 rows -> 16 n-blocks -> 8 pairs
// Fragment-packed bias+mask (pre-multiplied by log2e): [w][h][mh][mt][nt][lane] -> float4
__device__ float4 g_bmf[NWIN * NHEADS * 2 * 2 * 8 * 32];   // 16 MB, L2-resident

// ---------------- merged prep kernel ----------------
__global__ void prep_all_k(const float* __restrict__ mask,
                           const float* __restrict__ bias_table,
                           const int* __restrict__ rel_index,
                           const float* __restrict__ qkv_w,
                           const float* __restrict__ proj_w) {
    int e = blockIdx.x * blockDim.x + threadIdx.x;   // 2^20 threads
    if (e < 24 * 8 * 32) {
        int lane = e & 31, kt = (e >> 5) & 7, nbp = e >> 8;
        int n0 = nbp * 16 + (lane >> 2);
        int n1 = n0 + 8;
        int k0 = kt * 16 + 2 * (lane & 3);
        const float* W0 = qkv_w + n0 * DIMC + k0;
        const float* W1 = qkv_w + n1 * DIMC + k0;
        __half2 a0 = __floats2half2_rn(W0[0], W0[1]);
        __half2 a1 = __floats2half2_rn(W0[8], W0[9]);
        __half2 b0 = __floats2half2_rn(W1[0], W1[1]);
        __half2 b1 = __floats2half2_rn(W1[8], W1[9]);
        g_wqkv4[e] = make_uint4(*(unsigned*)&a0, *(unsigned*)&a1,
                                *(unsigned*)&b0, *(unsigned*)&b1);
    }
    if (e < 8 * 8 * 32) {
        int lane = e & 31, kt = (e >> 5) & 7, nbp = e >> 8;
        int n0 = nbp * 16 + (lane >> 2);
        int n1 = n0 + 8;
        int k0 = kt * 16 + 2 * (lane & 3);
        const float* W0 = proj_w + n0 * DIMC + k0;
        const float* W1 = proj_w + n1 * DIMC + k0;
        __half2 a0 = __floats2half2_rn(W0[0], W0[1]);
        __half2 a1 = __floats2half2_rn(W0[8], W0[9]);
        __half2 b0 = __floats2half2_rn(W1[0], W1[1]);
        __half2 b1 = __floats2half2_rn(W1[8], W1[9]);
        g_wproj4[e] = make_uint4(*(unsigned*)&a0, *(unsigned*)&a1,
                                 *(unsigned*)&b0, *(unsigned*)&b1);
    }
    // bmf: e linear over [w][h][mh][mt][nt][lane]; values pre-scaled by log2e
    {
        int lane = e & 31;
        int nt = (e >> 5) & 7;
        int mt = (e >> 8) & 1;
        int mh = (e >> 9) & 1;
        int h  = (e >> 10) & 3;
        int w  = e >> 12;
        int r0  = mh * 32 + mt * 16 + (lane >> 2);
        int col = nt * 8 + (lane & 3) * 2;
        const float* mw = mask + (size_t)w * 64 * 64;
        float v00 = mw[r0 * 64 + col]       + bias_table[rel_index[r0 * 64 + col] * NHEADS + h];
        float v01 = mw[r0 * 64 + col + 1]   + bias_table[rel_index[r0 * 64 + col + 1] * NHEADS + h];
        float v10 = mw[(r0 + 8) * 64 + col] + bias_table[rel_index[(r0 + 8) * 64 + col] * NHEADS + h];
        float v11 = mw[(r0 + 8) * 64 + col + 1]
                  + bias_table[rel_index[(r0 + 8) * 64 + col + 1] * NHEADS + h];
        g_bmf[e] = make_float4(v00 * LOG2E, v01 * LOG2E, v10 * LOG2E, v11 * LOG2E);
    }
}

// ---------------- helpers ----------------
__device__ __forceinline__ unsigned h2u(__half2 v) {
    return *reinterpret_cast<unsigned*>(&v);
}
__device__ __forceinline__ void mma_16816(float c[4], const unsigned a[4],
                                          const unsigned b0, const unsigned b1) {
    asm volatile(
        "mma.sync.aligned.m16n8k16.row.col.f32.f16.f16.f32 "
        "{%0,%1,%2,%3}, {%4,%5,%6,%7}, {%8,%9}, {%0,%1,%2,%3};\n"
        : "+f"(c[0]), "+f"(c[1]), "+f"(c[2]), "+f"(c[3])
        : "r"(a[0]), "r"(a[1]), "r"(a[2]), "r"(a[3]), "r"(b0), "r"(b1));
}
__device__ __forceinline__ void ldsm4(unsigned r[4], const __half* p) {
    unsigned a = (unsigned)__cvta_generic_to_shared(p);
    asm volatile("ldmatrix.sync.aligned.m8n8.x4.shared.b16 {%0,%1,%2,%3}, [%4];\n"
                 : "=r"(r[0]), "=r"(r[1]), "=r"(r[2]), "=r"(r[3]) : "r"(a));
}

// SMEM layout (bytes)
#define SM_XH  0       // [64][136] half = 17408  -> later oh
#define SM_KH  17408   // [64][136] half
#define SM_VT  34816   // [128][72] half = 18432 (vt[d][m])
#define SM_OH  0       // overlays xh
#define SMEM_BYTES 53248

// ---------------- main fused kernel: 1 window per CTA, 2 CTAs/SM ----------------
__global__ void __launch_bounds__(256, 2)
swin_attn_kernel(const float* __restrict__ x,
                 const float* __restrict__ qkv_b,
                 const float* __restrict__ proj_b,
                 float* __restrict__ out) {
    extern __shared__ char smem[];
    __half* xh = (__half*)(smem + SM_XH);
    __half* kh = (__half*)(smem + SM_KH);
    __half* vt = (__half*)(smem + SM_VT);
    __half* oh = (__half*)(smem + SM_OH);

    const int tid  = threadIdx.x;
    const int lane = tid & 31;
    const int warp = tid >> 5;
    const int l4   = lane >> 2;
    const int lm   = lane & 3;
    const int b    = blockIdx.x;

    const int arow = (lane & 7) + (lane & 8);
    const int acol = (lane & 16) ? 8 : 0;
    const int brow = (lane & 7) + ((lane & 16) ? 8 : 0);
    const int bcol = (lane & 8) ? 8 : 0;

    // unified warp mapping for ALL phases: head h, M-half mh
    const int h  = warp >> 1;
    const int mh = warp & 1;

    // ---- phase 0: x tile -> fp16 smem ----
    {
        const float4* xg = (const float4*)(x + (size_t)b * NTOK * DIMC);
#pragma unroll
        for (int i = 0; i < 8; ++i) {
            int idx = tid + i * 256;
            float4 v = __ldcs(xg + idx);
            int row = idx >> 5;
            int col = (idx & 31) << 2;
            __half2 h0 = __floats2half2_rn(v.x, v.y);
            __half2 h1 = __floats2half2_rn(v.z, v.w);
            *(uint2*)(xh + row * 136 + col) = make_uint2(h2u(h0), h2u(h1));
        }
    }
    __syncthreads();   // sync #1

    // q A-frags, built in registers by phase 1, consumed by phase 2
    unsigned aq[2][2][4];

    // ---- phase 1: QKV GEMM; warp computes its OWN q/k/v head slices ----
    {
        float cq[2][4][4], ck[2][4][4], cv[2][4][4];
#pragma unroll
        for (int a = 0; a < 2; ++a)
#pragma unroll
            for (int t = 0; t < 4; ++t)
#pragma unroll
                for (int r = 0; r < 4; ++r) {
                    cq[a][t][r] = 0.f; ck[a][t][r] = 0.f; cv[a][t][r] = 0.f;
                }

#pragma unroll
        for (int ktg = 0; ktg < 8; ++ktg) {
            int kc = ktg * 16;
            unsigned a0[4], a1[4];
            ldsm4(a0, xh + (mh * 32 + arow) * 136 + kc + acol);
            ldsm4(a1, xh + (mh * 32 + 16 + arow) * 136 + kc + acol);
#pragma unroll
            for (int p = 0; p < 2; ++p) {       // q
                uint4 f = __ldg(&g_wqkv4[(((h * 2 + p) * 8 + ktg) << 5) + lane]);
                mma_16816(cq[0][2 * p],     a0, f.x, f.y);
                mma_16816(cq[1][2 * p],     a1, f.x, f.y);
                mma_16816(cq[0][2 * p + 1], a0, f.z, f.w);
                mma_16816(cq[1][2 * p + 1], a1, f.z, f.w);
            }
#pragma unroll
            for (int p = 0; p < 2; ++p) {       // k
                uint4 f = __ldg(&g_wqkv4[(((8 + h * 2 + p) * 8 + ktg) << 5) + lane]);
                mma_16816(ck[0][2 * p],     a0, f.x, f.y);
                mma_16816(ck[1][2 * p],     a1, f.x, f.y);
                mma_16816(ck[0][2 * p + 1], a0, f.z, f.w);
                mma_16816(ck[1][2 * p + 1], a1, f.z, f.w);
            }
#pragma unroll
            for (int p = 0; p < 2; ++p) {       // v
                uint4 f = __ldg(&g_wqkv4[(((16 + h * 2 + p) * 8 + ktg) << 5) + lane]);
                mma_16816(cv[0][2 * p],     a0, f.x, f.y);
                mma_16816(cv[1][2 * p],     a1, f.x, f.y);
                mma_16816(cv[0][2 * p + 1], a0, f.z, f.w);
                mma_16816(cv[1][2 * p + 1], a1, f.z, f.w);
            }
        }

        // epilogue: k -> kh (head-dim cols h*32..+31, rows mh*32..+31)
#pragma unroll
        for (int mt = 0; mt < 2; ++mt)
#pragma unroll
            for (int nb = 0; nb < 4; ++nb) {
                int col = h * 32 + nb * 8 + lm * 2;
                int r0 = mh * 32 + mt * 16 + l4;
                float2 bv = *(const float2*)(qkv_b + 128 + col);
                *(__half2*)(kh + r0 * 136 + col) =
                    __floats2half2_rn(ck[mt][nb][0] + bv.x, ck[mt][nb][1] + bv.y);
                *(__half2*)(kh + (r0 + 8) * 136 + col) =
                    __floats2half2_rn(ck[mt][nb][2] + bv.x, ck[mt][nb][3] + bv.y);
            }
        // epilogue: v -> vt (transposed)
#pragma unroll
        for (int mt = 0; mt < 2; ++mt)
#pragma unroll
            for (int nb = 0; nb < 4; ++nb) {
                int d  = h * 32 + nb * 8 + lm * 2;
                int r0 = mh * 32 + mt * 16 + l4;
                float2 bv = *(const float2*)(qkv_b + 256 + d);
                vt[d * 72 + r0]           = __float2half_rn(cv[mt][nb][0] + bv.x);
                vt[(d + 1) * 72 + r0]     = __float2half_rn(cv[mt][nb][1] + bv.y);
                vt[d * 72 + r0 + 8]       = __float2half_rn(cv[mt][nb][2] + bv.x);
                vt[(d + 1) * 72 + r0 + 8] = __float2half_rn(cv[mt][nb][3] + bv.y);
            }
        // epilogue: q -> A-frags in registers (bias + scale folded, log2 domain)
        const float qsc = ATT_SCALE * LOG2E;
#pragma unroll
        for (int mt = 0; mt < 2; ++mt)
#pragma unroll
            for (int kt = 0; kt < 2; ++kt) {
                int col0 = h * 32 + (2 * kt) * 8 + lm * 2;
                float2 b0 = *(const float2*)(qkv_b + col0);
                float2 b1 = *(const float2*)(qkv_b + col0 + 8);
                aq[mt][kt][0] = h2u(__floats2half2_rn((cq[mt][2 * kt][0] + b0.x) * qsc,
                                                      (cq[mt][2 * kt][1] + b0.y) * qsc));
                aq[mt][kt][1] = h2u(__floats2half2_rn((cq[mt][2 * kt][2] + b0.x) * qsc,
                                                      (cq[mt][2 * kt][3] + b0.y) * qsc));
                aq[mt][kt][2] = h2u(__floats2half2_rn((cq[mt][2 * kt + 1][0] + b1.x) * qsc,
                                                      (cq[mt][2 * kt + 1][1] + b1.y) * qsc));
                aq[mt][kt][3] = h2u(__floats2half2_rn((cq[mt][2 * kt + 1][2] + b1.x) * qsc,
                                                      (cq[mt][2 * kt + 1][3] + b1.y) * qsc));
            }
    }
    __syncthreads();   // sync #2

    // ---- phase 2: attention (q in registers; S seeded with bias+mask) ----
    {
        const int rowbase = mh * 32;

        // seed S accumulators with (bias+mask)*log2e — mma accumulates on top
        const float4* bmf = g_bmf
            + ((((size_t)(b & 255) * NHEADS + h) * 2 + mh) * 2) * 8 * 32;
        float s[2][8][4];
#pragma unroll
        for (int mt = 0; mt < 2; ++mt)
#pragma unroll
            for (int nt = 0; nt < 8; ++nt) {
                float4 bv = __ldg(&bmf[(mt * 8 + nt) * 32 + lane]);
                s[mt][nt][0] = bv.x;
                s[mt][nt][1] = bv.y;
                s[mt][nt][2] = bv.z;
                s[mt][nt][3] = bv.w;
            }

        // S += Q @ K^T (q in registers, pre-scaled into log2 domain)
#pragma unroll
        for (int kt = 0; kt < 2; ++kt) {
            int kc = h * 32 + kt * 16;
#pragma unroll
            for (int p = 0; p < 4; ++p) {
                unsigned r[4];
                ldsm4(r, kh + (p * 16 + brow) * 136 + kc + bcol);
                mma_16816(s[0][2 * p],     aq[0][kt], r[0], r[1]);
                mma_16816(s[1][2 * p],     aq[1][kt], r[0], r[1]);
                mma_16816(s[0][2 * p + 1], aq[0][kt], r[2], r[3]);
                mma_16816(s[1][2 * p + 1], aq[1][kt], r[2], r[3]);
            }
        }

        // softmax in exp2 domain
        float rmax[4] = {-1e30f, -1e30f, -1e30f, -1e30f};
#pragma unroll
        for (int mt = 0; mt < 2; ++mt)
#pragma unroll
            for (int nt = 0; nt < 8; ++nt) {
                rmax[mt * 2]     = fmaxf(rmax[mt * 2],     fmaxf(s[mt][nt][0], s[mt][nt][1]));
                rmax[mt * 2 + 1] = fmaxf(rmax[mt * 2 + 1], fmaxf(s[mt][nt][2], s[mt][nt][3]));
            }
#pragma unroll
        for (int i = 0; i < 4; ++i) {
            rmax[i] = fmaxf(rmax[i], __shfl_xor_sync(0xffffffffu, rmax[i], 1));
            rmax[i] = fmaxf(rmax[i], __shfl_xor_sync(0xffffffffu, rmax[i], 2));
        }
        float rsum[4] = {0.f, 0.f, 0.f, 0.f};
#pragma unroll
        for (int mt = 0; mt < 2; ++mt)
#pragma unroll
            for (int nt = 0; nt < 8; ++nt) {
                s[mt][nt][0] = exp2f(s[mt][nt][0] - rmax[mt * 2]);
                s[mt][nt][1] = exp2f(s[mt][nt][1] - rmax[mt * 2]);
                s[mt][nt][2] = exp2f(s[mt][nt][2] - rmax[mt * 2 + 1]);
                s[mt][nt][3] = exp2f(s[mt][nt][3] - rmax[mt * 2 + 1]);
                rsum[mt * 2]     += s[mt][nt][0] + s[mt][nt][1];
                rsum[mt * 2 + 1] += s[mt][nt][2] + s[mt][nt][3];
            }
#pragma unroll
        for (int i = 0; i < 4; ++i) {
            rsum[i] += __shfl_xor_sync(0xffffffffu, rsum[i], 1);
            rsum[i] += __shfl_xor_sync(0xffffffffu, rsum[i], 2);
        }
        float rinv[4];
#pragma unroll
        for (int i = 0; i < 4; ++i) rinv[i] = 1.0f / rsum[i];

        // repack normalized P into A fragments
        unsigned pa[2][4][4];
#pragma unroll
        for (int mt = 0; mt < 2; ++mt)
#pragma unroll
            for (int k2 = 0; k2 < 4; ++k2) {
                pa[mt][k2][0] = h2u(__floats2half2_rn(s[mt][2 * k2][0] * rinv[2 * mt],
                                                      s[mt][2 * k2][1] * rinv[2 * mt]));
                pa[mt][k2][1] = h2u(__floats2half2_rn(s[mt][2 * k2][2] * rinv[2 * mt + 1],
                                                      s[mt][2 * k2][3] * rinv[2 * mt + 1]));
                pa[mt][k2][2] = h2u(__floats2half2_rn(s[mt][2 * k2 + 1][0] * rinv[2 * mt],
                                                      s[mt][2 * k2 + 1][1] * rinv[2 * mt]));
                pa[mt][k2][3] = h2u(__floats2half2_rn(s[mt][2 * k2 + 1][2] * rinv[2 * mt + 1],
                                                      s[mt][2 * k2 + 1][3] * rinv[2 * mt + 1]));
            }

        // O = P @ V (vt transposed layout)
        float o[2][4][4];
#pragma unroll
        for (int a = 0; a < 2; ++a)
#pragma unroll
            for (int t = 0; t < 4; ++t)
#pragma unroll
                for (int r = 0; r < 4; ++r) o[a][t][r] = 0.f;
#pragma unroll
        for (int k2 = 0; k2 < 4; ++k2)
#pragma unroll
            for (int p = 0; p < 2; ++p) {
                unsigned r[4];
                ldsm4(r, vt + (h * 32 + p * 16 + brow) * 72 + k2 * 16 + bcol);
                mma_16816(o[0][2 * p],     pa[0][k2], r[0], r[1]);
                mma_16816(o[1][2 * p],     pa[1][k2], r[0], r[1]);
                mma_16816(o[0][2 * p + 1], pa[0][k2], r[2], r[3]);
                mma_16816(o[1][2 * p + 1], pa[1][k2], r[2], r[3]);
            }
#pragma unroll
        for (int mt = 0; mt < 2; ++mt)
#pragma unroll
            for (int nt = 0; nt < 4; ++nt) {
                int col = h * 32 + nt * 8 + lm * 2;
                int r0 = rowbase + mt * 16 + l4;
                *(__half2*)(oh + r0 * 136 + col) =
                    __floats2half2_rn(o[mt][nt][0], o[mt][nt][1]);
                *(__half2*)(oh + (r0 + 8) * 136 + col) =
                    __floats2half2_rn(o[mt][nt][2], o[mt][nt][3]);
            }
    }
    __syncthreads();   // sync #3

    // ---- phase 3: out = O @ Wproj^T + proj_b (pure ldsm, R12 form) ----
    {
        float c[2][4][4];
#pragma unroll
        for (int a = 0; a < 2; ++a)
#pragma unroll
            for (int t = 0; t < 4; ++t)
#pragma unroll
                for (int r = 0; r < 4; ++r) c[a][t][r] = 0.f;

#pragma unroll
        for (int ktg = 0; ktg < 8; ++ktg) {
            int kc = ktg * 16;
            unsigned a0[4], a1[4];
            ldsm4(a0, oh + (mh * 32 + arow) * 136 + kc + acol);
            ldsm4(a1, oh + (mh * 32 + 16 + arow) * 136 + kc + acol);
#pragma unroll
            for (int p = 0; p < 2; ++p) {
                uint4 f = __ldg(&g_wproj4[(((h * 2 + p) * 8 + ktg) << 5) + lane]);
                mma_16816(c[0][2 * p],     a0, f.x, f.y);
                mma_16816(c[1][2 * p],     a1, f.x, f.y);
                mma_16816(c[0][2 * p + 1], a0, f.z, f.w);
                mma_16816(c[1][2 * p + 1], a1, f.z, f.w);
            }
        }

        float* og = out + (size_t)b * NTOK * DIMC;
#pragma unroll
        for (int mt = 0; mt < 2; ++mt)
#pragma unroll
            for (int nt = 0; nt < 4; ++nt) {
                int col = h * 32 + nt * 8 + lm * 2;
                int r0 = mh * 32 + mt * 16 + l4;
                float2 pb = *(const float2*)(proj_b + col);
                float2 v0 = {c[mt][nt][0] + pb.x, c[mt][nt][1] + pb.y};
                float2 v1 = {c[mt][nt][2] + pb.x, c[mt][nt][3] + pb.y};
                __stcs((float2*)(og + r0 * 128 + col), v0);
                __stcs((float2*)(og + (r0 + 8) * 128 + col), v1);
            }
    }
}

// ---------------- launch ----------------
extern "C" void kernel_launch(void* const* d_in, const int* in_sizes, int n_in,
                              void* d_out, int out_size) {
    const float* x       = (const float*)d_in[0];
    const float* mask    = (const float*)d_in[1];
    const float* qkv_w   = (const float*)d_in[2];
    const float* qkv_b   = (const float*)d_in[3];
    const float* proj_w  = (const float*)d_in[4];
    const float* proj_b  = (const float*)d_in[5];
    const float* bias_t  = (const float*)d_in[6];
    const int*   rel_idx = (const int*)d_in[7];
    float* out = (float*)d_out;

    prep_all_k<<<4096, 256>>>(mask, bias_t, rel_idx, qkv_w, proj_w);

    cudaFuncSetAttribute(swin_attn_kernel,
                         cudaFuncAttributeMaxDynamicSharedMemorySize, SMEM_BYTES);
    swin_attn_kernel<<<NWINDOWS, 256, SMEM_BYTES>>>(x, qkv_b, proj_b, out);
}